// round 5
// baseline (speedup 1.0000x reference)
#include <cuda_runtime.h>
#include <math.h>

#define NN   50000
#define EE   400000
#define INC  128
#define D1   256
#define HH   4
#define HD   64
#define GG   64
#define OUTC 10

// ---------------- scratch (device globals; no allocation allowed) ----------------
__device__ float g_q   [(size_t)NN * D1];
__device__ float g_k   [(size_t)NN * D1];
__device__ float g_v   [(size_t)NN * D1];
__device__ float g_skip[(size_t)NN * D1];
__device__ float g_h   [(size_t)NN * D1];
__device__ int   g_deg [NN];
__device__ int   g_off [NN + 1];
__device__ int   g_cur [NN];
__device__ int   g_csrc[EE];
__device__ float g_pool[(size_t)GG * D1];
__device__ float g_cnt [GG];

__device__ __forceinline__ float eluf(float x) { return x > 0.f ? x : expm1f(x); }

// ---------------- packed f32x2 helpers (Blackwell FFMA2 via PTX) ----------------
__device__ __forceinline__ unsigned long long pack_dup(float x)
{
    unsigned long long r;
    asm("mov.b64 %0, {%1, %1};" : "=l"(r) : "f"(x));
    return r;
}
__device__ __forceinline__ void ffma2(unsigned long long& d, unsigned long long a,
                                      unsigned long long b)
{
    asm("fma.rn.f32x2 %0, %1, %2, %0;" : "+l"(d) : "l"(a), "l"(b));
}

// ---------------- SGEMM: C[M,N] = A[M,K] @ W[K,N] + bias ----------------
// 128x128 tile, BK=16, 256 threads, 8x8 micro-tile, FFMA2 inner product.
__global__ __launch_bounds__(256, 2)
void sgemm128_kernel(const float* __restrict__ A, const float* __restrict__ W,
                     const float* __restrict__ bias, float* __restrict__ C,
                     int M, int K, int N)
{
    __shared__ float As[16][132];   // transposed: As[k][row], padded
    __shared__ float Bs[16][128];   // Bs[k][col]

    const int tid = threadIdx.x;
    const int bm = blockIdx.x, bn = blockIdx.y;
    const int tx = tid & 15, ty = tid >> 4;

    // acc2[i][j] = (C[i][2j], C[i][2j+1]) packed pairs, 8 rows x 4 pairs
    unsigned long long acc2[8][4];
#pragma unroll
    for (int i = 0; i < 8; i++)
#pragma unroll
        for (int j = 0; j < 4; j++) acc2[i][j] = 0ull;

    for (int kk = 0; kk < K; kk += 16) {
#pragma unroll
        for (int i = 0; i < 2; i++) {
            int idx = tid + i * 256;
            int ar = idx >> 2, ac = (idx & 3) << 2;
            int grow = bm * 128 + ar;
            float4 av = make_float4(0.f, 0.f, 0.f, 0.f);
            if (grow < M) av = *(const float4*)(A + (size_t)grow * K + kk + ac);
            As[ac + 0][ar] = av.x;
            As[ac + 1][ar] = av.y;
            As[ac + 2][ar] = av.z;
            As[ac + 3][ar] = av.w;

            int br = idx >> 5, bc = (idx & 31) << 2;
            float4 wv = *(const float4*)(W + (size_t)(kk + br) * N + bn * 128 + bc);
            *(float4*)&Bs[br][bc] = wv;
        }
        __syncthreads();

#pragma unroll
        for (int k2 = 0; k2 < 16; k2++) {
            float a[8];
            *(float4*)(a)     = *(const float4*)&As[k2][ty * 4];
            *(float4*)(a + 4) = *(const float4*)&As[k2][64 + ty * 4];
            // b pairs: reinterpret the two float4 column fragments as 4 f32x2
            unsigned long long bp[4];
            *(ulonglong2*)(bp)     = *(const ulonglong2*)&Bs[k2][tx * 4];
            *(ulonglong2*)(bp + 2) = *(const ulonglong2*)&Bs[k2][64 + tx * 4];
#pragma unroll
            for (int i = 0; i < 8; i++) {
                unsigned long long ap = pack_dup(a[i]);
#pragma unroll
                for (int j = 0; j < 4; j++)
                    ffma2(acc2[i][j], ap, bp[j]);
            }
        }
        __syncthreads();
    }

    float4 b0 = *(const float4*)(bias + bn * 128 + tx * 4);
    float4 b1 = *(const float4*)(bias + bn * 128 + 64 + tx * 4);
#pragma unroll
    for (int i = 0; i < 8; i++) {
        int row = bm * 128 + ((i < 4) ? (ty * 4 + i) : (64 + ty * 4 + (i - 4)));
        if (row < M) {
            const float2* p0 = (const float2*)&acc2[i][0];
            const float2* p1 = (const float2*)&acc2[i][2];
            float4 o0 = make_float4(p0[0].x + b0.x, p0[0].y + b0.y,
                                    p0[1].x + b0.z, p0[1].y + b0.w);
            float4 o1 = make_float4(p1[0].x + b1.x, p1[0].y + b1.y,
                                    p1[1].x + b1.z, p1[1].y + b1.w);
            *(float4*)(C + (size_t)row * N + bn * 128 + tx * 4) = o0;
            *(float4*)(C + (size_t)row * N + bn * 128 + 64 + tx * 4) = o1;
        }
    }
}

// ---------------- CSR build (by dst), once per launch ----------------
__global__ void zero_deg_kernel(int* deg)
{
    int i = blockIdx.x * blockDim.x + threadIdx.x;
    if (i < NN) deg[i] = 0;
}

__global__ void hist_kernel(const int* __restrict__ dst, int* __restrict__ deg)
{
    int e = blockIdx.x * blockDim.x + threadIdx.x;
    if (e < EE) atomicAdd(&deg[dst[e]], 1);
}

// single block, 1024 threads: exclusive scan of deg -> off, copy -> cur
__global__ void scan_kernel(const int* __restrict__ deg, int* __restrict__ off,
                            int* __restrict__ cur)
{
    __shared__ int sums[1024];
    const int C = (NN + 1023) / 1024;  // 49
    int t = threadIdx.x;
    int b0 = t * C, b1 = min(b0 + C, NN);
    int s = 0;
    for (int i = b0; i < b1; i++) s += deg[i];
    sums[t] = s;
    __syncthreads();
    for (int st = 1; st < 1024; st <<= 1) {
        int v = (t >= st) ? sums[t - st] : 0;
        __syncthreads();
        sums[t] += v;
        __syncthreads();
    }
    int base = (t == 0) ? 0 : sums[t - 1];
    for (int i = b0; i < b1; i++) {
        off[i] = base;
        cur[i] = base;
        base += deg[i];
    }
    if (t == 1023) off[NN] = sums[1023];
}

__global__ void fill_kernel(const int* __restrict__ src, const int* __restrict__ dst,
                            int* __restrict__ cur, int* __restrict__ csrc)
{
    int e = blockIdx.x * blockDim.x + threadIdx.x;
    if (e >= EE) return;
    int d = dst[e];
    int pos = atomicAdd(&cur[d], 1);
    csrc[pos] = src[e];
}

// ---------------- fused node-centric attention ----------------
// one warp per node: q row in registers, loop incoming edges, gather k/v rows,
// in-warp softmax (no max shift; logits are small), accumulate num/den in regs.
__global__ __launch_bounds__(256)
void attn_kernel(const float* __restrict__ q, const float* __restrict__ k,
                 const float* __restrict__ v, const float* __restrict__ skip,
                 const int* __restrict__ off, const int* __restrict__ csrc,
                 float* __restrict__ out)
{
    int node = (blockIdx.x * blockDim.x + threadIdx.x) >> 5;
    if (node >= NN) return;
    int lane = threadIdx.x & 31;

    const float4* qp = (const float4*)(q + (size_t)node * D1) + lane * 2;
    float4 qa = qp[0], qb = qp[1];

    float n0 = 0.f, n1 = 0.f, n2 = 0.f, n3 = 0.f;
    float n4 = 0.f, n5 = 0.f, n6 = 0.f, n7 = 0.f;
    float den = 0.f;

    int beg = off[node], end = off[node + 1];
    for (int p = beg; p < end; ++p) {
        int s = csrc[p];
        const float4* kp = (const float4*)(k + (size_t)s * D1) + lane * 2;
        const float4* vp = (const float4*)(v + (size_t)s * D1) + lane * 2;
        float4 ka = kp[0], kb = kp[1];
        float4 va = vp[0], vb = vp[1];
        float d = qa.x * ka.x + qa.y * ka.y + qa.z * ka.z + qa.w * ka.w
                + qb.x * kb.x + qb.y * kb.y + qb.z * kb.z + qb.w * kb.w;
        // reduce over the 8-lane head subgroup
        d += __shfl_xor_sync(0xffffffffu, d, 1);
        d += __shfl_xor_sync(0xffffffffu, d, 2);
        d += __shfl_xor_sync(0xffffffffu, d, 4);
        float ex = __expf(d * 0.125f);   // 1/sqrt(64)
        n0 += ex * va.x; n1 += ex * va.y; n2 += ex * va.z; n3 += ex * va.w;
        n4 += ex * vb.x; n5 += ex * vb.y; n6 += ex * vb.z; n7 += ex * vb.w;
        den += ex;
    }

    float inv = (end > beg) ? 1.f / den : 0.f;
    const float4* sp = (const float4*)(skip + (size_t)node * D1) + lane * 2;
    float4 sa = sp[0], sb = sp[1];
    float4 oa, ob;
    oa.x = eluf(n0 * inv + sa.x);
    oa.y = eluf(n1 * inv + sa.y);
    oa.z = eluf(n2 * inv + sa.z);
    oa.w = eluf(n3 * inv + sa.w);
    ob.x = eluf(n4 * inv + sb.x);
    ob.y = eluf(n5 * inv + sb.y);
    ob.z = eluf(n6 * inv + sb.z);
    ob.w = eluf(n7 * inv + sb.w);
    float4* op = (float4*)(out + (size_t)node * D1) + lane * 2;
    op[0] = oa;
    op[1] = ob;
}

// ---------------- pooling ----------------
__global__ void zero_pool_kernel(float* pool, float* cnt)
{
    int i = blockIdx.x * blockDim.x + threadIdx.x;
    if (i < GG * D1) pool[i] = 0.f;
    if (i < GG) cnt[i] = 0.f;
}

__global__ void count_kernel(const int* __restrict__ batch, float* __restrict__ cnt)
{
    int n = blockIdx.x * blockDim.x + threadIdx.x;
    if (n < NN) atomicAdd(&cnt[batch[n]], 1.0f);
}

// block = 256 threads (one channel each), 64 consecutive nodes; batch sorted.
__global__ void pool_kernel(const float* __restrict__ h, const int* __restrict__ batch,
                            float* __restrict__ pool)
{
    int n0 = blockIdx.x * 64;
    if (n0 >= NN) return;
    int c = threadIdx.x;
    float acc = 0.f;
    int curg = batch[n0];
    for (int i = 0; i < 64; i++) {
        int n = n0 + i;
        if (n >= NN) break;
        int g = batch[n];
        if (g != curg) {
            atomicAdd(&pool[(size_t)curg * D1 + c], acc);
            acc = 0.f;
            curg = g;
        }
        acc += h[(size_t)n * D1 + c];
    }
    atomicAdd(&pool[(size_t)curg * D1 + c], acc);
}

// ---------------- classifier + log_softmax ----------------
__global__ void final_kernel(const float* __restrict__ pool, const float* __restrict__ cnt,
                             const float* __restrict__ Wl, const float* __restrict__ bl,
                             float* __restrict__ out)
{
    int g = blockIdx.x, t = threadIdx.x;
    __shared__ float red[256];
    __shared__ float logits[OUTC + 1];
    float invc = 1.0f / fmaxf(cnt[g], 1.0f);
    float p = pool[(size_t)g * D1 + t] * invc;
    for (int o = 0; o < OUTC; o++) {
        red[t] = p * Wl[t * OUTC + o];
        __syncthreads();
        for (int st = 128; st > 0; st >>= 1) {
            if (t < st) red[t] += red[t + st];
            __syncthreads();
        }
        if (t == 0) logits[o] = red[0] + bl[o];
        __syncthreads();
    }
    if (t == 0) {
        float m = -1e30f;
        for (int o = 0; o < OUTC; o++) m = fmaxf(m, logits[o]);
        float s = 0.f;
        for (int o = 0; o < OUTC; o++) s += expf(logits[o] - m);
        logits[OUTC] = m + logf(s);
    }
    __syncthreads();
    if (t < OUTC) out[g * OUTC + t] = logits[t] - logits[OUTC];
}

// ---------------- host-side orchestration ----------------
static void run_gemm(const float* A, const float* W, const float* b, float* C,
                     int M, int K, int N)
{
    dim3 grid((M + 127) / 128, N / 128);
    sgemm128_kernel<<<grid, 256>>>(A, W, b, C, M, K, N);
}

static void run_layer(const float* xin, int K,
                      const float* Wq, const float* bq, const float* Wk, const float* bk,
                      const float* Wv, const float* bv, const float* Ws, const float* bs,
                      const int* off, const int* csrc,
                      float* q, float* k, float* v, float* skip, float* hout)
{
    run_gemm(xin, Wq, bq, q, NN, K, D1);
    run_gemm(xin, Wk, bk, k, NN, K, D1);
    run_gemm(xin, Wv, bv, v, NN, K, D1);
    run_gemm(xin, Ws, bs, skip, NN, K, D1);
    attn_kernel<<<(NN * 32 + 255) / 256, 256>>>(q, k, v, skip, off, csrc, hout);
}

extern "C" void kernel_launch(void* const* d_in, const int* in_sizes, int n_in,
                              void* d_out, int out_size)
{
    const float* x     = (const float*)d_in[0];
    const int*   ei    = (const int*)d_in[1];
    const int*   batch = (const int*)d_in[2];
    const float* Wq1 = (const float*)d_in[3],  *bq1 = (const float*)d_in[4];
    const float* Wk1 = (const float*)d_in[5],  *bk1 = (const float*)d_in[6];
    const float* Wv1 = (const float*)d_in[7],  *bv1 = (const float*)d_in[8];
    const float* Ws1 = (const float*)d_in[9],  *bs1 = (const float*)d_in[10];
    const float* Wq2 = (const float*)d_in[11], *bq2 = (const float*)d_in[12];
    const float* Wk2 = (const float*)d_in[13], *bk2 = (const float*)d_in[14];
    const float* Wv2 = (const float*)d_in[15], *bv2 = (const float*)d_in[16];
    const float* Ws2 = (const float*)d_in[17], *bs2 = (const float*)d_in[18];
    const float* Wl  = (const float*)d_in[19], *bl  = (const float*)d_in[20];
    float* out = (float*)d_out;

    const int* src = ei;        // edge_index[0]
    const int* dst = ei + EE;   // edge_index[1]

    float *q, *k, *v, *skip, *h, *pool, *cnt;
    int *deg, *off, *cur, *csrc;
    cudaGetSymbolAddress((void**)&q,    g_q);
    cudaGetSymbolAddress((void**)&k,    g_k);
    cudaGetSymbolAddress((void**)&v,    g_v);
    cudaGetSymbolAddress((void**)&skip, g_skip);
    cudaGetSymbolAddress((void**)&h,    g_h);
    cudaGetSymbolAddress((void**)&deg,  g_deg);
    cudaGetSymbolAddress((void**)&off,  g_off);
    cudaGetSymbolAddress((void**)&cur,  g_cur);
    cudaGetSymbolAddress((void**)&csrc, g_csrc);
    cudaGetSymbolAddress((void**)&pool, g_pool);
    cudaGetSymbolAddress((void**)&cnt,  g_cnt);

    // CSR build (shared by both layers)
    zero_deg_kernel<<<(NN + 255) / 256, 256>>>(deg);
    hist_kernel<<<(EE + 255) / 256, 256>>>(dst, deg);
    scan_kernel<<<1, 1024>>>(deg, off, cur);
    fill_kernel<<<(EE + 255) / 256, 256>>>(src, dst, cur, csrc);

    // layer 1: x[N,128] -> h[N,256]
    run_layer(x, INC, Wq1, bq1, Wk1, bk1, Wv1, bv1, Ws1, bs1,
              off, csrc, q, k, v, skip, h);
    // layer 2: h[N,256] -> h[N,256] (h consumed by GEMMs before attn writes it)
    run_layer(h, D1, Wq2, bq2, Wk2, bk2, Wv2, bv2, Ws2, bs2,
              off, csrc, q, k, v, skip, h);

    // mean pool per graph + classifier
    zero_pool_kernel<<<(GG * D1 + 255) / 256, 256>>>(pool, cnt);
    count_kernel<<<(NN + 255) / 256, 256>>>(batch, cnt);
    pool_kernel<<<(NN + 63) / 64, 256>>>(h, batch, pool);
    final_kernel<<<GG, 256>>>(pool, cnt, Wl, bl, out);
}

// round 8
// speedup vs baseline: 1.4964x; 1.4964x over previous
#include <cuda_runtime.h>
#include <math.h>

#define NN   50000
#define EE   400000
#define INC  128
#define D1   256
#define HH   4
#define HD   64
#define GG   64
#define OUTC 10

// ---------------- scratch (device globals; no allocation allowed) ----------------
__device__ float g_q   [(size_t)NN * D1];
__device__ float g_k   [(size_t)NN * D1];
__device__ float g_v   [(size_t)NN * D1];
__device__ float g_skip[(size_t)NN * D1];
__device__ float g_h   [(size_t)NN * D1];
__device__ int   g_deg [NN];
__device__ int   g_off [NN + 1];
__device__ int   g_cur [NN];
__device__ int   g_csrc[EE];
__device__ float g_pool[(size_t)GG * D1];
__device__ float g_cnt [GG];

__device__ __forceinline__ float eluf(float x) { return x > 0.f ? x : expm1f(x); }

__device__ __forceinline__ void cp_async16(void* smem_dst, const void* gmem_src)
{
    unsigned saddr = (unsigned)__cvta_generic_to_shared(smem_dst);
    asm volatile("cp.async.cg.shared.global [%0], [%1], 16;"
                 :: "r"(saddr), "l"(gmem_src));
}
__device__ __forceinline__ void cp_async_commit() { asm volatile("cp.async.commit_group;"); }
__device__ __forceinline__ void cp_async_wait0()  { asm volatile("cp.async.wait_group 0;" ::: "memory"); }

// ---------------- fused 4-GEMM: C[i][M,256] = A[M,K] @ W[i][K,256] + b[i] ----------
// grid = (ceil(M/128), 8); blockIdx.y: bits[2:1]=which gemm, bit0=column half.
// 128x128 tile, BK=16, 256 threads, 8x8 micro-tile, double-buffered smem.
struct GemmBatch {
    const float* W[4];
    const float* B[4];
    float*       C[4];
};

__global__ __launch_bounds__(256, 2)
void sgemm4_kernel(const float* __restrict__ A, GemmBatch gb, int M, int K)
{
    __shared__ float As[2][16][132];   // transposed: As[buf][k][row], padded
    __shared__ float Bs[2][16][128];   // Bs[buf][k][col]

    const int tid = threadIdx.x;
    const int bm = blockIdx.x;
    const int wi = blockIdx.y >> 1;
    const int bn = blockIdx.y & 1;
    const int tx = tid & 15, ty = tid >> 4;

    const float* __restrict__ W = gb.W[wi];
    const float* __restrict__ bias = gb.B[wi];
    float* __restrict__ C = gb.C[wi];

    // per-thread load indices
    const int ar0 = (tid * 2) >> 2,        ac0 = ((tid * 2) & 3) << 2;       // A part 0
    const int ar1 = (tid * 2 + 1) >> 2,    ac1 = ((tid * 2 + 1) & 3) << 2;   // A part 1
    const int br0 = tid >> 5,              bc0 = (tid & 31) << 2;            // B part 0
    const int br1 = (tid + 256) >> 5,      bc1 = (tid & 31) << 2;            // B part 1
    const int grow0 = bm * 128 + ar0, grow1 = bm * 128 + ar1;

    float acc[8][8];
#pragma unroll
    for (int i = 0; i < 8; i++)
#pragma unroll
        for (int j = 0; j < 8; j++) acc[i][j] = 0.f;

    const int T = K >> 4;

    // ---- prologue: tile 0 ----
    float4 a0 = make_float4(0.f, 0.f, 0.f, 0.f), a1 = a0;
    if (grow0 < M) a0 = *(const float4*)(A + (size_t)grow0 * K + ac0);
    if (grow1 < M) a1 = *(const float4*)(A + (size_t)grow1 * K + ac1);
    cp_async16(&Bs[0][br0][bc0], W + (size_t)br0 * D1 + bn * 128 + bc0);
    cp_async16(&Bs[0][br1][bc1], W + (size_t)br1 * D1 + bn * 128 + bc1);
    cp_async_commit();
    As[0][ac0 + 0][ar0] = a0.x; As[0][ac0 + 1][ar0] = a0.y;
    As[0][ac0 + 2][ar0] = a0.z; As[0][ac0 + 3][ar0] = a0.w;
    As[0][ac1 + 0][ar1] = a1.x; As[0][ac1 + 1][ar1] = a1.y;
    As[0][ac1 + 2][ar1] = a1.z; As[0][ac1 + 3][ar1] = a1.w;
    cp_async_wait0();
    __syncthreads();

    int cur = 0;
    for (int t = 0; t < T; t++) {
        const int nxt = cur ^ 1;
        float4 na0, na1;
        const bool more = (t + 1 < T);
        if (more) {
            const int kk = (t + 1) << 4;
            cp_async16(&Bs[nxt][br0][bc0], W + (size_t)(kk + br0) * D1 + bn * 128 + bc0);
            cp_async16(&Bs[nxt][br1][bc1], W + (size_t)(kk + br1) * D1 + bn * 128 + bc1);
            cp_async_commit();
            na0 = make_float4(0.f, 0.f, 0.f, 0.f); na1 = na0;
            if (grow0 < M) na0 = *(const float4*)(A + (size_t)grow0 * K + kk + ac0);
            if (grow1 < M) na1 = *(const float4*)(A + (size_t)grow1 * K + kk + ac1);
        }

#pragma unroll
        for (int k2 = 0; k2 < 16; k2++) {
            float a[8], b[8];
            *(float4*)(a)     = *(const float4*)&As[cur][k2][ty * 4];
            *(float4*)(a + 4) = *(const float4*)&As[cur][k2][64 + ty * 4];
            *(float4*)(b)     = *(const float4*)&Bs[cur][k2][tx * 4];
            *(float4*)(b + 4) = *(const float4*)&Bs[cur][k2][64 + tx * 4];
#pragma unroll
            for (int i = 0; i < 8; i++)
#pragma unroll
                for (int j = 0; j < 8; j++)
                    acc[i][j] += a[i] * b[j];
        }

        if (more) {
            As[nxt][ac0 + 0][ar0] = na0.x; As[nxt][ac0 + 1][ar0] = na0.y;
            As[nxt][ac0 + 2][ar0] = na0.z; As[nxt][ac0 + 3][ar0] = na0.w;
            As[nxt][ac1 + 0][ar1] = na1.x; As[nxt][ac1 + 1][ar1] = na1.y;
            As[nxt][ac1 + 2][ar1] = na1.z; As[nxt][ac1 + 3][ar1] = na1.w;
            cp_async_wait0();
        }
        __syncthreads();
        cur = nxt;
    }

    float4 b0 = *(const float4*)(bias + bn * 128 + tx * 4);
    float4 b1 = *(const float4*)(bias + bn * 128 + 64 + tx * 4);
#pragma unroll
    for (int i = 0; i < 8; i++) {
        int row = bm * 128 + ((i < 4) ? (ty * 4 + i) : (64 + ty * 4 + (i - 4)));
        if (row < M) {
            float4 o0 = make_float4(acc[i][0] + b0.x, acc[i][1] + b0.y,
                                    acc[i][2] + b0.z, acc[i][3] + b0.w);
            float4 o1 = make_float4(acc[i][4] + b1.x, acc[i][5] + b1.y,
                                    acc[i][6] + b1.z, acc[i][7] + b1.w);
            *(float4*)(C + (size_t)row * D1 + bn * 128 + tx * 4) = o0;
            *(float4*)(C + (size_t)row * D1 + bn * 128 + 64 + tx * 4) = o1;
        }
    }
}

// ---------------- CSR build (by dst), once per launch ----------------
__global__ void zero_deg_kernel(int* deg)
{
    int i = blockIdx.x * blockDim.x + threadIdx.x;
    if (i < NN) deg[i] = 0;
}

__global__ void hist_kernel(const int* __restrict__ dst, int* __restrict__ deg)
{
    int e = blockIdx.x * blockDim.x + threadIdx.x;
    if (e < EE) atomicAdd(&deg[dst[e]], 1);
}

// single block, 1024 threads: exclusive scan of deg -> off, copy -> cur
__global__ void scan_kernel(const int* __restrict__ deg, int* __restrict__ off,
                            int* __restrict__ cur)
{
    __shared__ int sums[1024];
    const int C = (NN + 1023) / 1024;  // 49
    int t = threadIdx.x;
    int b0 = t * C, b1 = min(b0 + C, NN);
    int s = 0;
    for (int i = b0; i < b1; i++) s += deg[i];
    sums[t] = s;
    __syncthreads();
    for (int st = 1; st < 1024; st <<= 1) {
        int v = (t >= st) ? sums[t - st] : 0;
        __syncthreads();
        sums[t] += v;
        __syncthreads();
    }
    int base = (t == 0) ? 0 : sums[t - 1];
    for (int i = b0; i < b1; i++) {
        off[i] = base;
        cur[i] = base;
        base += deg[i];
    }
    if (t == 1023) off[NN] = sums[1023];
}

__global__ void fill_kernel(const int* __restrict__ src, const int* __restrict__ dst,
                            int* __restrict__ cur, int* __restrict__ csrc)
{
    int e = blockIdx.x * blockDim.x + threadIdx.x;
    if (e >= EE) return;
    int d = dst[e];
    int pos = atomicAdd(&cur[d], 1);
    csrc[pos] = src[e];
}

// ---------------- fused node-centric attention (2-deep pipeline) ----------------
__global__ __launch_bounds__(256)
void attn_kernel(const float* __restrict__ q, const float* __restrict__ k,
                 const float* __restrict__ v, const float* __restrict__ skip,
                 const int* __restrict__ off, const int* __restrict__ csrc,
                 float* __restrict__ out)
{
    int node = (blockIdx.x * blockDim.x + threadIdx.x) >> 5;
    if (node >= NN) return;
    int lane = threadIdx.x & 31;

    const float4* qp = (const float4*)(q + (size_t)node * D1) + lane * 2;
    float4 qa = qp[0], qb = qp[1];
    const float4* sp = (const float4*)(skip + (size_t)node * D1) + lane * 2;
    float4 sa = sp[0], sb = sp[1];

    float n0 = 0.f, n1 = 0.f, n2 = 0.f, n3 = 0.f;
    float n4 = 0.f, n5 = 0.f, n6 = 0.f, n7 = 0.f;
    float den = 0.f;

    const int beg = off[node], end = off[node + 1];
    const int last = end - 1;

    float4 ka, kb, va, vb;
    if (beg < end) {
        int s = csrc[beg];
        const float4* kp = (const float4*)(k + (size_t)s * D1) + lane * 2;
        const float4* vp = (const float4*)(v + (size_t)s * D1) + lane * 2;
        ka = kp[0]; kb = kp[1]; va = vp[0]; vb = vp[1];
    }

    for (int p = beg; p < end; ++p) {
        // prefetch next edge's rows while computing this one
        int pn = (p + 1 < end) ? (p + 1) : last;
        int s2 = csrc[pn];
        const float4* kp2 = (const float4*)(k + (size_t)s2 * D1) + lane * 2;
        const float4* vp2 = (const float4*)(v + (size_t)s2 * D1) + lane * 2;
        float4 ka2 = kp2[0], kb2 = kp2[1], va2 = vp2[0], vb2 = vp2[1];

        float d = qa.x * ka.x + qa.y * ka.y + qa.z * ka.z + qa.w * ka.w
                + qb.x * kb.x + qb.y * kb.y + qb.z * kb.z + qb.w * kb.w;
        d += __shfl_xor_sync(0xffffffffu, d, 1);
        d += __shfl_xor_sync(0xffffffffu, d, 2);
        d += __shfl_xor_sync(0xffffffffu, d, 4);
        float ex = __expf(d * 0.125f);   // 1/sqrt(64)
        n0 += ex * va.x; n1 += ex * va.y; n2 += ex * va.z; n3 += ex * va.w;
        n4 += ex * vb.x; n5 += ex * vb.y; n6 += ex * vb.z; n7 += ex * vb.w;
        den += ex;

        ka = ka2; kb = kb2; va = va2; vb = vb2;
    }

    float inv = (end > beg) ? 1.f / den : 0.f;
    float4 oa, ob;
    oa.x = eluf(n0 * inv + sa.x);
    oa.y = eluf(n1 * inv + sa.y);
    oa.z = eluf(n2 * inv + sa.z);
    oa.w = eluf(n3 * inv + sa.w);
    ob.x = eluf(n4 * inv + sb.x);
    ob.y = eluf(n5 * inv + sb.y);
    ob.z = eluf(n6 * inv + sb.z);
    ob.w = eluf(n7 * inv + sb.w);
    float4* op = (float4*)(out + (size_t)node * D1) + lane * 2;
    op[0] = oa;
    op[1] = ob;
}

// ---------------- pooling ----------------
__global__ void zero_pool_kernel(float* pool, float* cnt)
{
    int i = blockIdx.x * blockDim.x + threadIdx.x;
    if (i < GG * D1) pool[i] = 0.f;
    if (i < GG) cnt[i] = 0.f;
}

__global__ void count_kernel(const int* __restrict__ batch, float* __restrict__ cnt)
{
    int n = blockIdx.x * blockDim.x + threadIdx.x;
    if (n < NN) atomicAdd(&cnt[batch[n]], 1.0f);
}

// block = 256 threads (one channel each), 64 consecutive nodes; batch sorted.
__global__ void pool_kernel(const float* __restrict__ h, const int* __restrict__ batch,
                            float* __restrict__ pool)
{
    int n0 = blockIdx.x * 64;
    if (n0 >= NN) return;
    int c = threadIdx.x;
    float acc = 0.f;
    int curg = batch[n0];
    for (int i = 0; i < 64; i++) {
        int n = n0 + i;
        if (n >= NN) break;
        int g = batch[n];
        if (g != curg) {
            atomicAdd(&pool[(size_t)curg * D1 + c], acc);
            acc = 0.f;
            curg = g;
        }
        acc += h[(size_t)n * D1 + c];
    }
    atomicAdd(&pool[(size_t)curg * D1 + c], acc);
}

// ---------------- classifier + log_softmax ----------------
__global__ void final_kernel(const float* __restrict__ pool, const float* __restrict__ cnt,
                             const float* __restrict__ Wl, const float* __restrict__ bl,
                             float* __restrict__ out)
{
    int g = blockIdx.x, t = threadIdx.x;
    __shared__ float red[256];
    __shared__ float logits[OUTC + 1];
    float invc = 1.0f / fmaxf(cnt[g], 1.0f);
    float p = pool[(size_t)g * D1 + t] * invc;
    for (int o = 0; o < OUTC; o++) {
        red[t] = p * Wl[t * OUTC + o];
        __syncthreads();
        for (int st = 128; st > 0; st >>= 1) {
            if (t < st) red[t] += red[t + st];
            __syncthreads();
        }
        if (t == 0) logits[o] = red[0] + bl[o];
        __syncthreads();
    }
    if (t == 0) {
        float m = -1e30f;
        for (int o = 0; o < OUTC; o++) m = fmaxf(m, logits[o]);
        float s = 0.f;
        for (int o = 0; o < OUTC; o++) s += expf(logits[o] - m);
        logits[OUTC] = m + logf(s);
    }
    __syncthreads();
    if (t < OUTC) out[g * OUTC + t] = logits[t] - logits[OUTC];
}

// ---------------- host-side orchestration ----------------
static void run_layer(const float* xin, int K,
                      const float* Wq, const float* bq, const float* Wk, const float* bk,
                      const float* Wv, const float* bv, const float* Ws, const float* bs,
                      const int* off, const int* csrc,
                      float* q, float* k, float* v, float* skip, float* hout)
{
    GemmBatch gb;
    gb.W[0] = Wq; gb.W[1] = Wk; gb.W[2] = Wv; gb.W[3] = Ws;
    gb.B[0] = bq; gb.B[1] = bk; gb.B[2] = bv; gb.B[3] = bs;
    gb.C[0] = q;  gb.C[1] = k;  gb.C[2] = v;  gb.C[3] = skip;
    dim3 grid((NN + 127) / 128, 8);
    sgemm4_kernel<<<grid, 256>>>(xin, gb, NN, K);
    attn_kernel<<<(NN * 32 + 255) / 256, 256>>>(q, k, v, skip, off, csrc, hout);
}

extern "C" void kernel_launch(void* const* d_in, const int* in_sizes, int n_in,
                              void* d_out, int out_size)
{
    const float* x     = (const float*)d_in[0];
    const int*   ei    = (const int*)d_in[1];
    const int*   batch = (const int*)d_in[2];
    const float* Wq1 = (const float*)d_in[3],  *bq1 = (const float*)d_in[4];
    const float* Wk1 = (const float*)d_in[5],  *bk1 = (const float*)d_in[6];
    const float* Wv1 = (const float*)d_in[7],  *bv1 = (const float*)d_in[8];
    const float* Ws1 = (const float*)d_in[9],  *bs1 = (const float*)d_in[10];
    const float* Wq2 = (const float*)d_in[11], *bq2 = (const float*)d_in[12];
    const float* Wk2 = (const float*)d_in[13], *bk2 = (const float*)d_in[14];
    const float* Wv2 = (const float*)d_in[15], *bv2 = (const float*)d_in[16];
    const float* Ws2 = (const float*)d_in[17], *bs2 = (const float*)d_in[18];
    const float* Wl  = (const float*)d_in[19], *bl  = (const float*)d_in[20];
    float* out = (float*)d_out;

    const int* src = ei;        // edge_index[0]
    const int* dst = ei + EE;   // edge_index[1]

    float *q, *k, *v, *skip, *h, *pool, *cnt;
    int *deg, *off, *cur, *csrc;
    cudaGetSymbolAddress((void**)&q,    g_q);
    cudaGetSymbolAddress((void**)&k,    g_k);
    cudaGetSymbolAddress((void**)&v,    g_v);
    cudaGetSymbolAddress((void**)&skip, g_skip);
    cudaGetSymbolAddress((void**)&h,    g_h);
    cudaGetSymbolAddress((void**)&deg,  g_deg);
    cudaGetSymbolAddress((void**)&off,  g_off);
    cudaGetSymbolAddress((void**)&cur,  g_cur);
    cudaGetSymbolAddress((void**)&csrc, g_csrc);
    cudaGetSymbolAddress((void**)&pool, g_pool);
    cudaGetSymbolAddress((void**)&cnt,  g_cnt);

    // CSR build (shared by both layers)
    zero_deg_kernel<<<(NN + 255) / 256, 256>>>(deg);
    hist_kernel<<<(EE + 255) / 256, 256>>>(dst, deg);
    scan_kernel<<<1, 1024>>>(deg, off, cur);
    fill_kernel<<<(EE + 255) / 256, 256>>>(src, dst, cur, csrc);

    // layer 1: x[N,128] -> h[N,256]
    run_layer(x, INC, Wq1, bq1, Wk1, bk1, Wv1, bv1, Ws1, bs1,
              off, csrc, q, k, v, skip, h);
    // layer 2: h[N,256] -> h[N,256] (h consumed by GEMMs before attn writes it)
    run_layer(h, D1, Wq2, bq2, Wk2, bk2, Wv2, bv2, Ws2, bs2,
              off, csrc, q, k, v, skip, h);

    // mean pool per graph + classifier
    zero_pool_kernel<<<(GG * D1 + 255) / 256, 256>>>(pool, cnt);
    count_kernel<<<(NN + 255) / 256, 256>>>(batch, cnt);
    pool_kernel<<<(NN + 63) / 64, 256>>>(h, batch, pool);
    final_kernel<<<GG, 256>>>(pool, cnt, Wl, bl, out);
}

// round 10
// speedup vs baseline: 2.0512x; 1.3707x over previous
#include <cuda_runtime.h>
#include <cuda_bf16.h>
#include <math.h>

#define NN   50000
#define EE   400000
#define INC  128
#define D1   256
#define HH   4
#define HD   64
#define GG   64
#define OUTC 10

// ---------------- scratch (device globals; no allocation allowed) ----------------
__device__ float    g_q   [(size_t)NN * D1];
__device__ float    g_k   [(size_t)NN * D1];
__device__ float    g_v   [(size_t)NN * D1];
__device__ float    g_skip[(size_t)NN * D1];
__device__ float    g_h   [(size_t)NN * D1];
__device__ int      g_deg [NN];
__device__ int      g_off [NN + 1];
__device__ int      g_cur [NN];
__device__ int      g_csrc[EE];
__device__ float    g_pool[(size_t)GG * D1];
__device__ float    g_cnt [GG];
// bf16 hi/lo split operands (packed 2 x bf16 per u32, k-contiguous)
__device__ unsigned g_Ahi[(size_t)NN * D1 / 2];
__device__ unsigned g_Alo[(size_t)NN * D1 / 2];
__device__ unsigned g_Wthi[4 * D1 * D1 / 2];
__device__ unsigned g_Wtlo[4 * D1 * D1 / 2];

__device__ __forceinline__ float eluf(float x) { return x > 0.f ? x : expm1f(x); }

__device__ __forceinline__ void cp_async16(void* smem_dst, const void* gmem_src)
{
    unsigned saddr = (unsigned)__cvta_generic_to_shared(smem_dst);
    asm volatile("cp.async.cg.shared.global [%0], [%1], 16;"
                 :: "r"(saddr), "l"(gmem_src));
}
__device__ __forceinline__ void cp_async_commit() { asm volatile("cp.async.commit_group;"); }
__device__ __forceinline__ void cp_async_wait0()  { asm volatile("cp.async.wait_group 0;" ::: "memory"); }

// ---------------- mma.sync helpers (sm_80-era PTX; valid on compute_103) ---------
__device__ __forceinline__ void ldsm_x4(unsigned addr, unsigned* r)
{
    asm volatile("ldmatrix.sync.aligned.m8n8.x4.shared.b16 {%0,%1,%2,%3}, [%4];"
                 : "=r"(r[0]), "=r"(r[1]), "=r"(r[2]), "=r"(r[3]) : "r"(addr));
}
__device__ __forceinline__ void ldsm_x2(unsigned addr, unsigned* r)
{
    asm volatile("ldmatrix.sync.aligned.m8n8.x2.shared.b16 {%0,%1}, [%2];"
                 : "=r"(r[0]), "=r"(r[1]) : "r"(addr));
}
__device__ __forceinline__ void mma_bf16(float* c, const unsigned* a, const unsigned* b)
{
    asm volatile("mma.sync.aligned.m16n8k16.row.col.f32.bf16.bf16.f32 "
                 "{%0,%1,%2,%3}, {%4,%5,%6,%7}, {%8,%9}, {%0,%1,%2,%3};"
                 : "+f"(c[0]), "+f"(c[1]), "+f"(c[2]), "+f"(c[3])
                 : "r"(a[0]), "r"(a[1]), "r"(a[2]), "r"(a[3]),
                   "r"(b[0]), "r"(b[1]));
}

// ---------------- fp32 -> bf16 hi/lo split (packed pairs) ----------------
__device__ __forceinline__ unsigned pack_bf16(__nv_bfloat16 a, __nv_bfloat16 b)
{
    return (unsigned)__bfloat16_as_ushort(a) | ((unsigned)__bfloat16_as_ushort(b) << 16);
}

__global__ void convA_kernel(const float* __restrict__ X, unsigned* __restrict__ Ahi,
                             unsigned* __restrict__ Alo, int n2)
{
    int i = blockIdx.x * blockDim.x + threadIdx.x;
    if (i >= n2) return;
    float2 x = ((const float2*)X)[i];
    __nv_bfloat16 h0 = __float2bfloat16(x.x);
    __nv_bfloat16 h1 = __float2bfloat16(x.y);
    __nv_bfloat16 l0 = __float2bfloat16(x.x - __bfloat162float(h0));
    __nv_bfloat16 l1 = __float2bfloat16(x.y - __bfloat162float(h1));
    Ahi[i] = pack_bf16(h0, h1);
    Alo[i] = pack_bf16(l0, l1);
}

struct WPtrs { const float* W[4]; };

// transpose W[K,256] -> Wt[256,K] (K-major rows) with hi/lo bf16 split
__global__ void convW_kernel(WPtrs wp, unsigned* __restrict__ Wthi,
                             unsigned* __restrict__ Wtlo, int K)
{
    __shared__ float t[32][33];
    int wi = blockIdx.z;
    const float* __restrict__ W = wp.W[wi];
    int n0 = blockIdx.x * 32, k0 = blockIdx.y * 32;
    for (int r = threadIdx.y; r < 32; r += 8)
        t[r][threadIdx.x] = W[(size_t)(k0 + r) * D1 + n0 + threadIdx.x];
    __syncthreads();
    int tid2 = threadIdx.y * 32 + threadIdx.x;
    int K2 = K >> 1;
    for (int i = tid2; i < 32 * 16; i += 256) {
        int n = i >> 4, kp = i & 15;
        float a = t[2 * kp][n], b = t[2 * kp + 1][n];
        __nv_bfloat16 ha = __float2bfloat16(a), hb = __float2bfloat16(b);
        __nv_bfloat16 la = __float2bfloat16(a - __bfloat162float(ha));
        __nv_bfloat16 lb = __float2bfloat16(b - __bfloat162float(hb));
        size_t o = (size_t)(wi * D1 + n0 + n) * K2 + (k0 >> 1) + kp;
        Wthi[o] = pack_bf16(ha, hb);
        Wtlo[o] = pack_bf16(la, lb);
    }
}

// ---------------- HMMA GEMM: C[wi][M,256] = A[M,K] @ W[wi][K,256] + b ------------
// grid = (ceil(M/128), 8); by: bits[2:1]=gemm idx, bit0=N half.
// CTA tile 128x128; 8 warps each 64x32; m16n8k16 bf16, 3-term hi/lo.
// smem chunk (BK=16): 4 sections x 128 rows x 48B (16 bf16 + 8B pad), double buffered.
struct TCOut {
    const float* bias[4];
    float*       C[4];
};

#define ROWB   48
#define SECB   (128 * ROWB)      // 6144
#define CHUNKB (4 * SECB)        // 24576
#define SMEM_MMA (2 * CHUNKB)    // 49152 (exactly the 48KB no-attr limit)

__global__ __launch_bounds__(256)
void gemm_mma_kernel(const unsigned* __restrict__ Ahi, const unsigned* __restrict__ Alo,
                     const unsigned* __restrict__ Wthi, const unsigned* __restrict__ Wtlo,
                     TCOut pr, int M, int K)
{
    extern __shared__ __align__(16) char smem[];
    const int tid = threadIdx.x, lane = tid & 31, wid = tid >> 5;
    const int bm = blockIdx.x, wi = blockIdx.y >> 1, bn = blockIdx.y & 1;
    const int warp_m = wid & 1, warp_n = wid >> 1;
    const int K2 = K >> 1, nkb = K >> 4;
    const unsigned sbase = (unsigned)__cvta_generic_to_shared(smem);

    // per-thread cp.async mapping: 4 x 16B per chunk
    const unsigned* gptr[4];
    unsigned sdst[4];
#pragma unroll
    for (int t = 0; t < 4; t++) {
        int id = tid + t * 256;
        int sec = id >> 8, sid = id & 255, row = sid >> 1, q = sid & 1;
        sdst[t] = sec * SECB + row * ROWB + q * 16;
        size_t rb;
        const unsigned* base;
        if (sec < 2) {
            int grow = bm * 128 + row;
            if (grow >= M) grow = M - 1;          // clamp: OOB rows never stored
            rb = (size_t)grow * K2;
            base = (sec == 0) ? Ahi : Alo;
        } else {
            int n = bn * 128 + row;
            rb = (size_t)(wi * D1 + n) * K2;
            base = (sec == 2) ? Wthi : Wtlo;
        }
        gptr[t] = base + rb + q * 4;
    }

    // fragment smem addresses (buf 0; buf 1 adds CHUNKB)
    unsigned aAh[4], aAl[4], aBh[4], aBl[4];
#pragma unroll
    for (int i = 0; i < 4; i++) {
        unsigned arow = warp_m * 64 + i * 16 + (lane & 15);
        unsigned aoff = arow * ROWB + ((lane >> 4) << 4);
        aAh[i] = sbase + aoff;
        aAl[i] = sbase + SECB + aoff;
        unsigned brow = warp_n * 32 + i * 8 + (lane & 7);
        unsigned boff = brow * ROWB + (((lane >> 3) & 1) << 4);
        aBh[i] = sbase + 2 * SECB + boff;
        aBl[i] = sbase + 3 * SECB + boff;
    }

    float acc[4][4][4];
#pragma unroll
    for (int i = 0; i < 4; i++)
#pragma unroll
        for (int j = 0; j < 4; j++)
#pragma unroll
            for (int e = 0; e < 4; e++) acc[i][j][e] = 0.f;

    // prologue: chunk 0 -> buf 0
#pragma unroll
    for (int t = 0; t < 4; t++) cp_async16(smem + sdst[t], gptr[t]);
    cp_async_commit();

    for (int kb = 0; kb < nkb; kb++) {
        const int cur = kb & 1;
        cp_async_wait0();
        __syncthreads();
        if (kb + 1 < nkb) {
            const unsigned bo = (cur ^ 1) * CHUNKB;
            const int go = (kb + 1) * 8;          // 8 u32 per chunk per row
#pragma unroll
            for (int t = 0; t < 4; t++)
                cp_async16(smem + bo + sdst[t], gptr[t] + go);
            cp_async_commit();
        }

        const unsigned bo = cur * CHUNKB;
        unsigned Ah[4][4], Al[4][4], Bh[4][2], Bl[4][2];
#pragma unroll
        for (int i = 0; i < 4; i++) {
            ldsm_x4(aAh[i] + bo, Ah[i]);
            ldsm_x4(aAl[i] + bo, Al[i]);
            ldsm_x2(aBh[i] + bo, Bh[i]);
            ldsm_x2(aBl[i] + bo, Bl[i]);
        }
#pragma unroll
        for (int i = 0; i < 4; i++)
#pragma unroll
            for (int j = 0; j < 4; j++) {
                mma_bf16(acc[i][j], Ah[i], Bh[j]);
                mma_bf16(acc[i][j], Ah[i], Bl[j]);
                mma_bf16(acc[i][j], Al[i], Bh[j]);
            }
        __syncthreads();
    }

    // epilogue
    const float* __restrict__ bias = pr.bias[wi];
    float* __restrict__ C = pr.C[wi];
    const int colbase = bn * 128 + warp_n * 32;
#pragma unroll
    for (int j = 0; j < 4; j++) {
        int c0 = colbase + j * 8 + (lane & 3) * 2;
        float bx = bias[c0], by = bias[c0 + 1];
#pragma unroll
        for (int i = 0; i < 4; i++) {
            int r0 = bm * 128 + warp_m * 64 + i * 16 + (lane >> 2);
            if (r0 < M) {
                float2 o = make_float2(acc[i][j][0] + bx, acc[i][j][1] + by);
                *(float2*)(C + (size_t)r0 * D1 + c0) = o;
            }
            int r1 = r0 + 8;
            if (r1 < M) {
                float2 o = make_float2(acc[i][j][2] + bx, acc[i][j][3] + by);
                *(float2*)(C + (size_t)r1 * D1 + c0) = o;
            }
        }
    }
}

// ---------------- CSR build (by dst), once per launch ----------------
__global__ void zero_deg_kernel(int* deg)
{
    int i = blockIdx.x * blockDim.x + threadIdx.x;
    if (i < NN) deg[i] = 0;
}

__global__ void hist_kernel(const int* __restrict__ dst, int* __restrict__ deg)
{
    int e = blockIdx.x * blockDim.x + threadIdx.x;
    if (e < EE) atomicAdd(&deg[dst[e]], 1);
}

__global__ void scan_kernel(const int* __restrict__ deg, int* __restrict__ off,
                            int* __restrict__ cur)
{
    __shared__ int sums[1024];
    const int C = (NN + 1023) / 1024;
    int t = threadIdx.x;
    int b0 = t * C, b1 = min(b0 + C, NN);
    int s = 0;
    for (int i = b0; i < b1; i++) s += deg[i];
    sums[t] = s;
    __syncthreads();
    for (int st = 1; st < 1024; st <<= 1) {
        int v = (t >= st) ? sums[t - st] : 0;
        __syncthreads();
        sums[t] += v;
        __syncthreads();
    }
    int base = (t == 0) ? 0 : sums[t - 1];
    for (int i = b0; i < b1; i++) {
        off[i] = base;
        cur[i] = base;
        base += deg[i];
    }
    if (t == 1023) off[NN] = sums[1023];
}

__global__ void fill_kernel(const int* __restrict__ src, const int* __restrict__ dst,
                            int* __restrict__ cur, int* __restrict__ csrc)
{
    int e = blockIdx.x * blockDim.x + threadIdx.x;
    if (e >= EE) return;
    int d = dst[e];
    int pos = atomicAdd(&cur[d], 1);
    csrc[pos] = src[e];
}

// ---------------- fused node-centric attention (2-deep pipeline) ----------------
__global__ __launch_bounds__(256)
void attn_kernel(const float* __restrict__ q, const float* __restrict__ k,
                 const float* __restrict__ v, const float* __restrict__ skip,
                 const int* __restrict__ off, const int* __restrict__ csrc,
                 float* __restrict__ out)
{
    int node = (blockIdx.x * blockDim.x + threadIdx.x) >> 5;
    if (node >= NN) return;
    int lane = threadIdx.x & 31;

    const float4* qp = (const float4*)(q + (size_t)node * D1) + lane * 2;
    float4 qa = qp[0], qb = qp[1];
    const float4* sp = (const float4*)(skip + (size_t)node * D1) + lane * 2;
    float4 sa = sp[0], sb = sp[1];

    float n0 = 0.f, n1 = 0.f, n2 = 0.f, n3 = 0.f;
    float n4 = 0.f, n5 = 0.f, n6 = 0.f, n7 = 0.f;
    float den = 0.f;

    const int beg = off[node], end = off[node + 1];
    const int last = end - 1;

    float4 ka, kb, va, vb;
    if (beg < end) {
        int s = csrc[beg];
        const float4* kp = (const float4*)(k + (size_t)s * D1) + lane * 2;
        const float4* vp = (const float4*)(v + (size_t)s * D1) + lane * 2;
        ka = kp[0]; kb = kp[1]; va = vp[0]; vb = vp[1];
    }

    for (int p = beg; p < end; ++p) {
        int pn = (p + 1 < end) ? (p + 1) : last;
        int s2 = csrc[pn];
        const float4* kp2 = (const float4*)(k + (size_t)s2 * D1) + lane * 2;
        const float4* vp2 = (const float4*)(v + (size_t)s2 * D1) + lane * 2;
        float4 ka2 = kp2[0], kb2 = kp2[1], va2 = vp2[0], vb2 = vp2[1];

        float d = qa.x * ka.x + qa.y * ka.y + qa.z * ka.z + qa.w * ka.w
                + qb.x * kb.x + qb.y * kb.y + qb.z * kb.z + qb.w * kb.w;
        d += __shfl_xor_sync(0xffffffffu, d, 1);
        d += __shfl_xor_sync(0xffffffffu, d, 2);
        d += __shfl_xor_sync(0xffffffffu, d, 4);
        float ex = __expf(d * 0.125f);
        n0 += ex * va.x; n1 += ex * va.y; n2 += ex * va.z; n3 += ex * va.w;
        n4 += ex * vb.x; n5 += ex * vb.y; n6 += ex * vb.z; n7 += ex * vb.w;
        den += ex;

        ka = ka2; kb = kb2; va = va2; vb = vb2;
    }

    float inv = (end > beg) ? 1.f / den : 0.f;
    float4 oa, ob;
    oa.x = eluf(n0 * inv + sa.x);
    oa.y = eluf(n1 * inv + sa.y);
    oa.z = eluf(n2 * inv + sa.z);
    oa.w = eluf(n3 * inv + sa.w);
    ob.x = eluf(n4 * inv + sb.x);
    ob.y = eluf(n5 * inv + sb.y);
    ob.z = eluf(n6 * inv + sb.z);
    ob.w = eluf(n7 * inv + sb.w);
    float4* op = (float4*)(out + (size_t)node * D1) + lane * 2;
    op[0] = oa;
    op[1] = ob;
}

// ---------------- pooling ----------------
__global__ void zero_pool_kernel(float* pool, float* cnt)
{
    int i = blockIdx.x * blockDim.x + threadIdx.x;
    if (i < GG * D1) pool[i] = 0.f;
    if (i < GG) cnt[i] = 0.f;
}

__global__ void count_kernel(const int* __restrict__ batch, float* __restrict__ cnt)
{
    int n = blockIdx.x * blockDim.x + threadIdx.x;
    if (n < NN) atomicAdd(&cnt[batch[n]], 1.0f);
}

__global__ void pool_kernel(const float* __restrict__ h, const int* __restrict__ batch,
                            float* __restrict__ pool)
{
    int n0 = blockIdx.x * 64;
    if (n0 >= NN) return;
    int c = threadIdx.x;
    float acc = 0.f;
    int curg = batch[n0];
    for (int i = 0; i < 64; i++) {
        int n = n0 + i;
        if (n >= NN) break;
        int g = batch[n];
        if (g != curg) {
            atomicAdd(&pool[(size_t)curg * D1 + c], acc);
            acc = 0.f;
            curg = g;
        }
        acc += h[(size_t)n * D1 + c];
    }
    atomicAdd(&pool[(size_t)curg * D1 + c], acc);
}

// ---------------- classifier + log_softmax ----------------
__global__ void final_kernel(const float* __restrict__ pool, const float* __restrict__ cnt,
                             const float* __restrict__ Wl, const float* __restrict__ bl,
                             float* __restrict__ out)
{
    int g = blockIdx.x, t = threadIdx.x;
    __shared__ float red[256];
    __shared__ float logits[OUTC + 1];
    float invc = 1.0f / fmaxf(cnt[g], 1.0f);
    float p = pool[(size_t)g * D1 + t] * invc;
    for (int o = 0; o < OUTC; o++) {
        red[t] = p * Wl[t * OUTC + o];
        __syncthreads();
        for (int st = 128; st > 0; st >>= 1) {
            if (t < st) red[t] += red[t + st];
            __syncthreads();
        }
        if (t == 0) logits[o] = red[0] + bl[o];
        __syncthreads();
    }
    if (t == 0) {
        float m = -1e30f;
        for (int o = 0; o < OUTC; o++) m = fmaxf(m, logits[o]);
        float s = 0.f;
        for (int o = 0; o < OUTC; o++) s += expf(logits[o] - m);
        logits[OUTC] = m + logf(s);
    }
    __syncthreads();
    if (t < OUTC) out[g * OUTC + t] = logits[t] - logits[OUTC];
}

// ---------------- host-side orchestration ----------------
static void run_layer_mma(const float* xin, int K,
                          const float* Wq, const float* bq, const float* Wk, const float* bk,
                          const float* Wv, const float* bv, const float* Ws, const float* bs,
                          const int* off, const int* csrc,
                          unsigned* Ahi, unsigned* Alo, unsigned* Wthi, unsigned* Wtlo,
                          float* q, float* k, float* v, float* skip, float* hout)
{
    int n2 = NN * K / 2;
    convA_kernel<<<(n2 + 255) / 256, 256>>>(xin, Ahi, Alo, n2);
    WPtrs wp; wp.W[0] = Wq; wp.W[1] = Wk; wp.W[2] = Wv; wp.W[3] = Ws;
    convW_kernel<<<dim3(D1 / 32, K / 32, 4), dim3(32, 8)>>>(wp, Wthi, Wtlo, K);

    TCOut pr;
    pr.bias[0] = bq; pr.bias[1] = bk; pr.bias[2] = bv; pr.bias[3] = bs;
    pr.C[0] = q;  pr.C[1] = k;  pr.C[2] = v;  pr.C[3] = skip;
    gemm_mma_kernel<<<dim3((NN + 127) / 128, 8), 256, SMEM_MMA>>>(
        Ahi, Alo, Wthi, Wtlo, pr, NN, K);

    attn_kernel<<<(NN * 32 + 255) / 256, 256>>>(q, k, v, skip, off, csrc, hout);
}

extern "C" void kernel_launch(void* const* d_in, const int* in_sizes, int n_in,
                              void* d_out, int out_size)
{
    const float* x     = (const float*)d_in[0];
    const int*   ei    = (const int*)d_in[1];
    const int*   batch = (const int*)d_in[2];
    const float* Wq1 = (const float*)d_in[3],  *bq1 = (const float*)d_in[4];
    const float* Wk1 = (const float*)d_in[5],  *bk1 = (const float*)d_in[6];
    const float* Wv1 = (const float*)d_in[7],  *bv1 = (const float*)d_in[8];
    const float* Ws1 = (const float*)d_in[9],  *bs1 = (const float*)d_in[10];
    const float* Wq2 = (const float*)d_in[11], *bq2 = (const float*)d_in[12];
    const float* Wk2 = (const float*)d_in[13], *bk2 = (const float*)d_in[14];
    const float* Wv2 = (const float*)d_in[15], *bv2 = (const float*)d_in[16];
    const float* Ws2 = (const float*)d_in[17], *bs2 = (const float*)d_in[18];
    const float* Wl  = (const float*)d_in[19], *bl  = (const float*)d_in[20];
    float* out = (float*)d_out;

    const int* src = ei;
    const int* dst = ei + EE;

    float *q, *k, *v, *skip, *h, *pool, *cnt;
    int *deg, *off, *cur, *csrc;
    unsigned *Ahi, *Alo, *Wthi, *Wtlo;
    cudaGetSymbolAddress((void**)&q,    g_q);
    cudaGetSymbolAddress((void**)&k,    g_k);
    cudaGetSymbolAddress((void**)&v,    g_v);
    cudaGetSymbolAddress((void**)&skip, g_skip);
    cudaGetSymbolAddress((void**)&h,    g_h);
    cudaGetSymbolAddress((void**)&deg,  g_deg);
    cudaGetSymbolAddress((void**)&off,  g_off);
    cudaGetSymbolAddress((void**)&cur,  g_cur);
    cudaGetSymbolAddress((void**)&csrc, g_csrc);
    cudaGetSymbolAddress((void**)&pool, g_pool);
    cudaGetSymbolAddress((void**)&cnt,  g_cnt);
    cudaGetSymbolAddress((void**)&Ahi,  g_Ahi);
    cudaGetSymbolAddress((void**)&Alo,  g_Alo);
    cudaGetSymbolAddress((void**)&Wthi, g_Wthi);
    cudaGetSymbolAddress((void**)&Wtlo, g_Wtlo);

    // CSR build (shared by both layers)
    zero_deg_kernel<<<(NN + 255) / 256, 256>>>(deg);
    hist_kernel<<<(EE + 255) / 256, 256>>>(dst, deg);
    scan_kernel<<<1, 1024>>>(deg, off, cur);
    fill_kernel<<<(EE + 255) / 256, 256>>>(src, dst, cur, csrc);

    // layer 1: x[N,128] -> h[N,256]
    run_layer_mma(x, INC, Wq1, bq1, Wk1, bk1, Wv1, bv1, Ws1, bs1,
                  off, csrc, Ahi, Alo, Wthi, Wtlo, q, k, v, skip, h);
    // layer 2: h[N,256] -> h[N,256]
    run_layer_mma(h, D1, Wq2, bq2, Wk2, bk2, Wv2, bv2, Ws2, bs2,
                  off, csrc, Ahi, Alo, Wthi, Wtlo, q, k, v, skip, h);

    // mean pool per graph + classifier
    zero_pool_kernel<<<(GG * D1 + 255) / 256, 256>>>(pool, cnt);
    count_kernel<<<(NN + 255) / 256, 256>>>(batch, cnt);
    pool_kernel<<<(NN + 63) / 64, 256>>>(h, batch, pool);
    final_kernel<<<GG, 256>>>(pool, cnt, Wl, bl, out);
}